// round 5
// baseline (speedup 1.0000x reference)
#include <cuda_runtime.h>
#include <math.h>
#include <stdint.h>

#define N_SEQ   256
#define T_LEN   128
#define EMBED   512
#define UNITS   512
#define GATEC   2048              // 4*UNITS
#define M_ALL   (N_SEQ * T_LEN)   // 32768

#define REC_CTAS  128
#define REC_THR   128
#define UW        16              // unit columns per CTA
#define KCHUNK    64
#define SH_PAD    68              // floats per staged row (64 + pad, 16B mult)
#define SU_FLOATS (512 * 4 * UW)              // [k][gate][uc] = 32768 floats
#define SH_FLOATS (REC_THR * SH_PAD)          // one buffer: 128 rows
#define SMEM_REC  ((SU_FLOATS + 2 * SH_FLOATS) * 4)   // 200704 bytes

typedef unsigned long long ull;

// ---------------- packed f32x2 helpers --------------------------------------
__device__ __forceinline__ ull pk2(float x, float y) {
    ull r; asm("mov.b64 %0, {%1,%2};" : "=l"(r) : "f"(x), "f"(y)); return r;
}
__device__ __forceinline__ void upk2(ull v, float& lo, float& hi) {
    asm("mov.b64 {%0,%1}, %2;" : "=f"(lo), "=f"(hi) : "l"(v));
}
__device__ __forceinline__ void ffma2(ull& d, ull a, ull b) {
    asm("fma.rn.f32x2 %0, %1, %2, %0;" : "+l"(d) : "l"(a), "l"(b));
}

// ---------------- cp.async helpers ------------------------------------------
__device__ __forceinline__ void cpasync16(uint32_t dst, const void* src) {
    asm volatile("cp.async.cg.shared.global [%0], [%1], 16;" :: "r"(dst), "l"(src));
}
__device__ __forceinline__ void cpcommit() {
    asm volatile("cp.async.commit_group;");
}
template <int N> __device__ __forceinline__ void cpwait() {
    asm volatile("cp.async.wait_group %0;" :: "n"(N));
}

// ---------------- scratch ---------------------------------------------------
__device__ float    g_xW[2][M_ALL][GATEC];     // x@W + b, per direction
__device__ float    g_h[2][2][N_SEQ][UNITS];   // [dir][parity][n][u]
__device__ unsigned g_bar;                     // global step barrier counter

__global__ void init_kernel() { g_bar = 0; }

// ---------------- fused embedding gather + input projection GEMM ------------
// (round-3 version: scalar FFMA, measured fastest)
__global__ void __launch_bounds__(256, 2)
xw_kernel(const int* __restrict__ x, const float* __restrict__ emb,
          const float* __restrict__ Wf, const float* __restrict__ bf,
          const float* __restrict__ Wb, const float* __restrict__ bb)
{
    const int nt  = blockIdx.x;
    const int mt  = blockIdx.y;
    const int dir = blockIdx.z;
    const float* __restrict__ W    = dir ? Wb : Wf;
    const float* __restrict__ bias = dir ? bb : bf;
    const int m0 = mt * 128;
    const int n0 = nt * 64;

    __shared__ float sa[32][132];
    __shared__ float sb[32][64];
    __shared__ int   sid[128];

    const int tid = threadIdx.x;
    if (tid < 128) sid[tid] = x[m0 + tid];
    __syncthreads();

    const int arow = tid & 127;
    const int aseg = (tid >> 7) * 16;
    const size_t aoff = (size_t)sid[arow] * EMBED + aseg;

    const int rg = (tid >> 4) * 8;
    const int cg = (tid & 15) * 4;

    float acc[8][4];
#pragma unroll
    for (int r = 0; r < 8; r++)
#pragma unroll
        for (int c = 0; c < 4; c++) acc[r][c] = 0.0f;

    for (int k0 = 0; k0 < EMBED; k0 += 32) {
#pragma unroll
        for (int i = 0; i < 4; i++) {
            float4 v = *(const float4*)(emb + aoff + k0 + i * 4);
            int kk = aseg + i * 4;
            sa[kk + 0][arow] = v.x;
            sa[kk + 1][arow] = v.y;
            sa[kk + 2][arow] = v.z;
            sa[kk + 3][arow] = v.w;
        }
#pragma unroll
        for (int j = 0; j < 2; j++) {
            int idx = tid * 2 + j;
            int kk  = idx >> 4;
            int cc  = (idx & 15) * 4;
            *(float4*)&sb[kk][cc] =
                *(const float4*)(W + (size_t)(k0 + kk) * GATEC + n0 + cc);
        }
        __syncthreads();

#pragma unroll 16
        for (int k = 0; k < 32; k++) {
            const float4 b4 = *(const float4*)&sb[k][cg];
            const float4 x0 = *(const float4*)&sa[k][rg];
            const float4 x1 = *(const float4*)&sa[k][rg + 4];
            const float av[8] = {x0.x, x0.y, x0.z, x0.w, x1.x, x1.y, x1.z, x1.w};
#pragma unroll
            for (int r = 0; r < 8; r++) {
                acc[r][0] = fmaf(av[r], b4.x, acc[r][0]);
                acc[r][1] = fmaf(av[r], b4.y, acc[r][1]);
                acc[r][2] = fmaf(av[r], b4.z, acc[r][2]);
                acc[r][3] = fmaf(av[r], b4.w, acc[r][3]);
            }
        }
        __syncthreads();
    }

    const float4 bsv = *(const float4*)(bias + n0 + cg);
#pragma unroll
    for (int r = 0; r < 8; r++) {
        const int row = m0 + rg + r;
        float4 o;
        o.x = acc[r][0] + bsv.x;
        o.y = acc[r][1] + bsv.y;
        o.z = acc[r][2] + bsv.z;
        o.w = acc[r][3] + bsv.w;
        *(float4*)&g_xW[dir][row][n0 + cg] = o;
    }
}

// ---------------- persistent bidirectional LSTM recurrence ------------------
__device__ __forceinline__ float sigmoidf_(float v) { return 1.0f / (1.0f + expf(-v)); }

__global__ void __launch_bounds__(REC_THR)
rec_kernel(const int* __restrict__ x,
           const float* __restrict__ Uf, const float* __restrict__ Ub,
           float* __restrict__ out)
{
    extern __shared__ float smem[];
    float* su = smem;                         // [512][4][UW]
    float* sh = smem + SU_FLOATS;             // 2 x [128 rows][SH_PAD]

    const int bid = blockIdx.x;
    const int dir = bid >> 6;                 // 0..1
    const int mt  = (bid >> 5) & 1;           // 0..1
    const int us  = bid & 31;                 // 0..31
    const int u0  = us * UW;
    const int m0  = mt * 128;
    const float* __restrict__ U = dir ? Ub : Uf;

    const int tid = threadIdx.x;
    const int rg  = tid >> 3;                 // 0..15 (row group; rows rg+16*i)
    const int ucg = tid & 7;                  // 0..7
    const int uc2 = ucg * 2;                  // column pair base

    const uint32_t sh_base = (uint32_t)__cvta_generic_to_shared(sh);

    // ---- one-time: load this CTA's U slice into smem: su[k][g][c] ----------
    for (int i = tid; i < 512 * UW; i += REC_THR) {
        int k = i >> 4, c = i & 15;
#pragma unroll
        for (int g = 0; g < 4; g++)
            su[(k * 4 + g) * UW + c] = U[(size_t)k * GATEC + g * UNITS + u0 + c];
    }

    // ---- zero owned state + h parity 0 -------------------------------------
    float c_reg[16], h_reg[16];
#pragma unroll
    for (int s = 0; s < 16; s++) { c_reg[s] = 0.0f; h_reg[s] = 0.0f; }
#pragma unroll
    for (int i = 0; i < 8; i++) {
        const int n = m0 + rg + 16 * i;
        *(float2*)&g_h[dir][0][n][u0 + uc2] = make_float2(0.0f, 0.0f);
    }

    // ---- global barrier helper state ---------------------------------------
    unsigned barcnt = 0;
    auto gbar = [&]() {
        __threadfence();
        __syncthreads();
        barcnt++;
        if (tid == 0) {
            atomicAdd(&g_bar, 1u);
            const unsigned target = barcnt * REC_CTAS;
            while (*(volatile unsigned*)&g_bar < target) __nanosleep(64);
        }
        __syncthreads();
        __threadfence();   // acquire: invalidate L1 so fresh h is observed
    };

    gbar();   // zeros + su visible everywhere

    for (int t = 0; t < T_LEN; t++) {
        const int pin  = t & 1;
        const int pout = pin ^ 1;
        const int tt   = dir ? (T_LEN - 1 - t) : t;
        const float* __restrict__ hin = &g_h[dir][pin][m0][0];

        ull acc[8][4];
#pragma unroll
        for (int i = 0; i < 8; i++)
#pragma unroll
            for (int g = 0; g < 4; g++) acc[i][g] = 0ull;

        // stage helper: chunk kc into buffer b (each thread = one row)
        auto stage = [&](int b, int kc) {
            const float* src = hin + (size_t)tid * UNITS + kc * KCHUNK;
            const uint32_t dst = sh_base + (uint32_t)((b * SH_FLOATS + tid * SH_PAD) * 4);
#pragma unroll
            for (int j = 0; j < 16; j++)
                cpasync16(dst + j * 16, src + j * 4);
            cpcommit();
        };

        stage(0, 0);
        stage(1, 1);
        int buf = 0;

        for (int kc = 0; kc < 8; kc++) {
            if (kc < 7) cpwait<1>(); else cpwait<0>();
            __syncthreads();

            const float* shb = sh + buf * SH_FLOATS;
            const float* sup = su + (size_t)(kc * KCHUNK) * 4 * UW + uc2;
#pragma unroll 8
            for (int k = 0; k < KCHUNK; k++) {
                const float* sk = sup + k * (4 * UW);
                const ull bI = *(const ull*)(sk + 0 * UW);
                const ull bF = *(const ull*)(sk + 1 * UW);
                const ull bG = *(const ull*)(sk + 2 * UW);
                const ull bO = *(const ull*)(sk + 3 * UW);
#pragma unroll
                for (int i = 0; i < 8; i++) {
                    const float a = shb[(rg + 16 * i) * SH_PAD + k];
                    const ull a2 = pk2(a, a);
                    ffma2(acc[i][0], a2, bI);
                    ffma2(acc[i][1], a2, bF);
                    ffma2(acc[i][2], a2, bG);
                    ffma2(acc[i][3], a2, bO);
                }
            }
            __syncthreads();
            if (kc + 2 < 8) stage(buf, kc + 2);
            buf ^= 1;
        }

        // ---- gate math + masked update (Keras: hold state when masked) -----
#pragma unroll
        for (int i = 0; i < 8; i++) {
            const int n   = m0 + rg + 16 * i;
            const int row = n * T_LEN + tt;
            const bool msk = (x[row] != 0);
            const float* xwp = &g_xW[dir][row][u0 + uc2];

            float zl[4], zh[4];
#pragma unroll
            for (int g = 0; g < 4; g++) upk2(acc[i][g], zl[g], zh[g]);
            float2 zi = *(const float2*)(xwp + 0 * UNITS);
            float2 zf = *(const float2*)(xwp + 1 * UNITS);
            float2 zg = *(const float2*)(xwp + 2 * UNITS);
            float2 zo = *(const float2*)(xwp + 3 * UNITS);
            zi.x += zl[0]; zi.y += zh[0];
            zf.x += zl[1]; zf.y += zh[1];
            zg.x += zl[2]; zg.y += zh[2];
            zo.x += zl[3]; zo.y += zh[3];

            float2 hnew;
#pragma unroll
            for (int j = 0; j < 2; j++) {
                const int s = i * 2 + j;
                const float vzi = j ? zi.y : zi.x;
                const float vzf = j ? zf.y : zf.x;
                const float vzg = j ? zg.y : zg.x;
                const float vzo = j ? zo.y : zo.x;
                float ig = sigmoidf_(vzi), fg = sigmoidf_(vzf);
                float gg = tanhf(vzg),     og = sigmoidf_(vzo);
                float cn = fmaf(fg, c_reg[s], ig * gg);
                float hn = og * tanhf(cn);
                if (!msk) { cn = c_reg[s]; hn = h_reg[s]; }
                c_reg[s] = cn;
                h_reg[s] = hn;
                if (j) hnew.y = hn; else hnew.x = hn;
            }
            *(float2*)&g_h[dir][pout][n][u0 + uc2] = hnew;
        }

        if (t < T_LEN - 1) gbar();
    }

    // ---- final output straight from registers: concat(h_fwd, h_bwd) --------
#pragma unroll
    for (int i = 0; i < 8; i++) {
        const int n = m0 + rg + 16 * i;
        float2 hv = make_float2(h_reg[2 * i], h_reg[2 * i + 1]);
        *(float2*)&out[(size_t)n * 1024 + dir * 512 + u0 + uc2] = hv;
    }
}

// ---------------- launch ----------------------------------------------------
extern "C" void kernel_launch(void* const* d_in, const int* in_sizes, int n_in,
                              void* d_out, int out_size)
{
    const int*   x   = (const int*)  d_in[0];
    const float* emb = (const float*)d_in[1];
    const float* Wf  = (const float*)d_in[2];
    const float* Uf  = (const float*)d_in[3];
    const float* bf  = (const float*)d_in[4];
    const float* Wb  = (const float*)d_in[5];
    const float* Ub  = (const float*)d_in[6];
    const float* bb  = (const float*)d_in[7];
    float* out = (float*)d_out;
    (void)in_sizes; (void)n_in; (void)out_size;

    cudaFuncSetAttribute(rec_kernel,
                         cudaFuncAttributeMaxDynamicSharedMemorySize, SMEM_REC);

    init_kernel<<<1, 1>>>();

    dim3 gx(32, 256, 2);
    xw_kernel<<<gx, 256>>>(x, emb, Wf, bf, Wb, bb);

    rec_kernel<<<REC_CTAS, REC_THR, SMEM_REC>>>(x, Uf, Ub, out);
}